// round 16
// baseline (speedup 1.0000x reference)
#include <cuda_runtime.h>
#include <cuda_bf16.h>
#include <cuda_fp16.h>
#include <stdint.h>

#define BB 4
#define SSQ 2048
#define DM 1024
#define NH 16
#define MR (BB*SSQ)

// ---------------------------------------------------------------------------
// Scratch
// ---------------------------------------------------------------------------
__device__ uint32_t g_wth[2*DM*512], g_wtl[2*DM*512];   // Wq,Wk transposed, bf16 split
__device__ uint32_t g_wtf[2*DM*512];                    // Wv,Wo transposed, fp16
__device__ uint32_t g_xh[2u*MR*512], g_xl[2u*MR*512];   // q,k inputs bf16 split
__device__ uint32_t g_xf[MR*512];                       // v input fp16
__device__ uint32_t g_Qf[MR*512], g_Kf[MR*512], g_Vf[MR*512], g_Aof[MR*512];
__device__ float g_cm[BB*NH*SSQ], g_cr[BB*NH*SSQ];

// ---------------------------------------------------------------------------
// helpers
// ---------------------------------------------------------------------------
__device__ __forceinline__ void split2(float x, float y, uint32_t& hi, uint32_t& lo){
    __nv_bfloat16 hx = __float2bfloat16(x);
    __nv_bfloat16 hy = __float2bfloat16(y);
    float rx = x - __bfloat162float(hx);
    float ry = y - __bfloat162float(hy);
    __nv_bfloat162 h2 = __halves2bfloat162(hx, hy);
    __nv_bfloat162 l2 = __halves2bfloat162(__float2bfloat16(rx), __float2bfloat16(ry));
    hi = *reinterpret_cast<uint32_t*>(&h2);
    lo = *reinterpret_cast<uint32_t*>(&l2);
}
__device__ __forceinline__ uint32_t packf16(float x, float y){
    __half2 h = __floats2half2_rn(x, y);
    return *reinterpret_cast<uint32_t*>(&h);
}

__device__ __forceinline__ void mma16(float* d,
    uint32_t a0, uint32_t a1, uint32_t a2, uint32_t a3, uint32_t b0, uint32_t b1)
{
    asm volatile(
        "mma.sync.aligned.m16n8k16.row.col.f32.bf16.bf16.f32 "
        "{%0,%1,%2,%3}, {%4,%5,%6,%7}, {%8,%9}, {%0,%1,%2,%3};\n"
        : "+f"(d[0]), "+f"(d[1]), "+f"(d[2]), "+f"(d[3])
        : "r"(a0), "r"(a1), "r"(a2), "r"(a3), "r"(b0), "r"(b1));
}
__device__ __forceinline__ void mmah(float* d,
    uint32_t a0, uint32_t a1, uint32_t a2, uint32_t a3, uint32_t b0, uint32_t b1)
{
    asm volatile(
        "mma.sync.aligned.m16n8k16.row.col.f32.f16.f16.f32 "
        "{%0,%1,%2,%3}, {%4,%5,%6,%7}, {%8,%9}, {%0,%1,%2,%3};\n"
        : "+f"(d[0]), "+f"(d[1]), "+f"(d[2]), "+f"(d[3])
        : "r"(a0), "r"(a1), "r"(a2), "r"(a3), "r"(b0), "r"(b1));
}

__device__ __forceinline__ uint32_t smem_u32(const void* p){
    uint32_t a;
    asm("{ .reg .u64 t; cvta.to.shared.u64 t, %1; cvt.u32.u64 %0, t; }" : "=r"(a) : "l"(p));
    return a;
}
__device__ __forceinline__ void ldsm4(uint32_t* r, uint32_t addr){
    asm volatile("ldmatrix.sync.aligned.m8n8.x4.shared.b16 {%0,%1,%2,%3}, [%4];"
        : "=r"(r[0]), "=r"(r[1]), "=r"(r[2]), "=r"(r[3]) : "r"(addr));
}
__device__ __forceinline__ void ldsm4t(uint32_t* r, uint32_t addr){
    asm volatile("ldmatrix.sync.aligned.m8n8.x4.trans.shared.b16 {%0,%1,%2,%3}, [%4];"
        : "=r"(r[0]), "=r"(r[1]), "=r"(r[2]), "=r"(r[3]) : "r"(addr));
}
__device__ __forceinline__ void cpa16(uint32_t dst, const void* src){
    asm volatile("cp.async.cg.shared.global [%0], [%1], 16;\n" :: "r"(dst), "l"(src));
}
#define CP_COMMIT asm volatile("cp.async.commit_group;\n" ::: "memory")
#define CP_WAIT0  asm volatile("cp.async.wait_group 0;\n" ::: "memory")

__device__ __forceinline__ int swo(int r, int c){
    return (r << 4) + (((c ^ ((r >> 1) & 3))) << 2);
}

// ---------------------------------------------------------------------------
// prepass
// ---------------------------------------------------------------------------
__global__ __launch_bounds__(256) void inprep3(const float* __restrict__ q,
    const float* __restrict__ k, const float* __restrict__ v)
{
    const int y = blockIdx.y;
    size_t i = (size_t)blockIdx.x*256 + threadIdx.x;
    if (y < 2){
        const float* in = y ? k : q;
        float2 vv = *(const float2*)(in + 2*i);
        uint32_t hh, ll; split2(vv.x, vv.y, hh, ll);
        g_xh[(size_t)y*MR*512 + i] = hh;
        g_xl[(size_t)y*MR*512 + i] = ll;
    } else {
        float2 vv = *(const float2*)(v + 2*i);
        g_xf[i] = packf16(vv.x, vv.y);
    }
}

// merged W prep: z=0,1 -> bf16 split (Wq,Wk); z=2,3 -> fp16 (Wv,Wo)
__global__ __launch_bounds__(256) void wprep_all(const float* __restrict__ Wq,
    const float* __restrict__ Wk, const float* __restrict__ Wv,
    const float* __restrict__ Wo)
{
    __shared__ float t[64][33];
    const int z = blockIdx.z;
    const float* W = (z == 0) ? Wq : (z == 1) ? Wk : (z == 2) ? Wv : Wo;
    const int k0 = blockIdx.x << 6, n0 = blockIdx.y << 5;
    const int tid = threadIdx.x;
#pragma unroll
    for (int i = 0; i < 8; i++){
        int v = i*256 + tid;
        t[v >> 5][v & 31] = W[(size_t)(k0 + (v >> 5))*DM + n0 + (v & 31)];
    }
    __syncthreads();
    const int n = tid >> 3, pi = (tid & 7) << 2;
    if (z < 2){
        uint4 H, L; uint32_t h, l;
        split2(t[2*pi][n],   t[2*pi+1][n], h, l); H.x = h; L.x = l;
        split2(t[2*pi+2][n], t[2*pi+3][n], h, l); H.y = h; L.y = l;
        split2(t[2*pi+4][n], t[2*pi+5][n], h, l); H.z = h; L.z = l;
        split2(t[2*pi+6][n], t[2*pi+7][n], h, l); H.w = h; L.w = l;
        size_t o = (size_t)z*DM*512 + (size_t)(n0 + n)*512 + (k0 >> 1) + pi;
        *(uint4*)(g_wth + o) = H;
        *(uint4*)(g_wtl + o) = L;
    } else {
        uint4 H;
        H.x = packf16(t[2*pi][n],   t[2*pi+1][n]);
        H.y = packf16(t[2*pi+2][n], t[2*pi+3][n]);
        H.z = packf16(t[2*pi+4][n], t[2*pi+5][n]);
        H.w = packf16(t[2*pi+6][n], t[2*pi+7][n]);
        *(uint4*)(g_wtf + (size_t)(z-2)*DM*512 + (size_t)(n0 + n)*512 + (k0 >> 1) + pi) = H;
    }
}

// ---------------------------------------------------------------------------
// proj_bf3_body: exact 3-pass split-bf16 GEMM, fp16 out. 2-stage cp.async,
// pass-major mma ordering. 256 thr, 8 warps 2x4, warp 64x32.
// ---------------------------------------------------------------------------
__device__ __forceinline__ void proj_bf3_body(
    const uint32_t* __restrict__ Ah, const uint32_t* __restrict__ Al,
    const uint32_t* __restrict__ Bh, const uint32_t* __restrict__ Bl,
    const float* __restrict__ bias, uint32_t* __restrict__ oh, uint32_t* S)
{
    const int tid = threadIdx.x, lane = tid & 31, w = tid >> 5;
    const int wy = w >> 2, wx = w & 3;
    const int brow = blockIdx.y << 7, bcol = blockIdx.x << 7;
    const uint32_t sb = smem_u32(S);

    const int srow = tid >> 1, sh = tid & 1;
    const int sw = (srow >> 1) & 3;
    const int st0 = (srow << 4) + (((2*sh)   ^ sw) << 2);
    const int st1 = (srow << 4) + (((2*sh+1) ^ sw) << 2);

    const uint32_t* gA0 = Ah + (size_t)(brow + srow)*512 + sh*8;
    const uint32_t* gA1 = Al + (size_t)(brow + srow)*512 + sh*8;
    const uint32_t* gB0 = Bh + (size_t)(bcol + srow)*512 + sh*8;
    const uint32_t* gB1 = Bl + (size_t)(bcol + srow)*512 + sh*8;

#define PSTAGE(s, B) do { \
        int o = (s) << 4; \
        cpa16(sb + 4*((B) + st0),        gA0 + o); cpa16(sb + 4*((B) + st1),        gA0 + o + 4); \
        cpa16(sb + 4*((B) + 2048 + st0), gA1 + o); cpa16(sb + 4*((B) + 2048 + st1), gA1 + o + 4); \
        cpa16(sb + 4*((B) + 4096 + st0), gB0 + o); cpa16(sb + 4*((B) + 4096 + st1), gB0 + o + 4); \
        cpa16(sb + 4*((B) + 6144 + st0), gB1 + o); cpa16(sb + 4*((B) + 6144 + st1), gB1 + o + 4); \
        CP_COMMIT; } while(0)

    float acc[4][4][4];
#pragma unroll
    for (int mt = 0; mt < 4; mt++)
#pragma unroll
        for (int nt = 0; nt < 4; nt++)
#pragma unroll
            for (int j = 0; j < 4; j++) acc[mt][nt][j] = 0.f;

    PSTAGE(0, 0);

    for (int it = 0; it < 32; it++){
        const int B = (it & 1) << 13;
        CP_WAIT0;
        __syncthreads();
        if (it < 31) PSTAGE(it + 1, ((it + 1) & 1) << 13);

        uint32_t bhv[4][4], blv[4][4];
#pragma unroll
        for (int nt = 0; nt < 4; nt++){
            int rB = wx*32 + nt*8 + (lane & 7);
            int cB = lane >> 3;
            uint32_t ad = sb + 4*(B + 4096 + swo(rB, cB));
            ldsm4(bhv[nt], ad);
            ldsm4(blv[nt], ad + 2048*4);
        }
#pragma unroll
        for (int kc = 0; kc < 2; kc++){
#pragma unroll
            for (int mt = 0; mt < 4; mt++){
                uint32_t ahv[4], alv[4];
                int rA = wy*64 + mt*16 + (lane & 15);
                int cA = 2*kc + (lane >> 4);
                uint32_t ad = sb + 4*(B + swo(rA, cA));
                ldsm4(ahv, ad);
                ldsm4(alv, ad + 2048*4);
#pragma unroll
                for (int nt = 0; nt < 4; nt++)
                    mma16(acc[mt][nt], ahv[0],ahv[1],ahv[2],ahv[3], bhv[nt][2*kc], bhv[nt][2*kc+1]);
#pragma unroll
                for (int nt = 0; nt < 4; nt++)
                    mma16(acc[mt][nt], alv[0],alv[1],alv[2],alv[3], bhv[nt][2*kc], bhv[nt][2*kc+1]);
#pragma unroll
                for (int nt = 0; nt < 4; nt++)
                    mma16(acc[mt][nt], ahv[0],ahv[1],ahv[2],ahv[3], blv[nt][2*kc], blv[nt][2*kc+1]);
            }
        }
    }
#undef PSTAGE

#pragma unroll
    for (int mt = 0; mt < 4; mt++)
#pragma unroll
        for (int nt = 0; nt < 4; nt++){
            int row = brow + wy*64 + mt*16 + (lane >> 2);
            int col = bcol + wx*32 + nt*8 + ((lane & 3) << 1);
            float b0 = bias[col], b1 = bias[col+1];
            oh[(size_t)row*512 + (col>>1)] =
                packf16(acc[mt][nt][0] + b0, acc[mt][nt][1] + b1);
            oh[(size_t)(row+8)*512 + (col>>1)] =
                packf16(acc[mt][nt][2] + b0, acc[mt][nt][3] + b1);
        }
}

// ---------------------------------------------------------------------------
// proj_f16_body: single-pass fp16 GEMM, 2-stage cp.async.
// ---------------------------------------------------------------------------
__device__ __forceinline__ void proj_f16_body(
    const uint32_t* __restrict__ Af, const uint32_t* __restrict__ Bf,
    const float* __restrict__ bias, uint32_t* __restrict__ oh,
    float* __restrict__ of, uint32_t* S)
{
    const int tid = threadIdx.x, lane = tid & 31, w = tid >> 5;
    const int wy = w >> 2, wx = w & 3;
    const int brow = blockIdx.y << 7, bcol = blockIdx.x << 7;
    const uint32_t sb = smem_u32(S);

    const int srow = tid >> 1, sh = tid & 1;
    const int sw = (srow >> 1) & 3;
    const int st0 = (srow << 4) + (((2*sh)   ^ sw) << 2);
    const int st1 = (srow << 4) + (((2*sh+1) ^ sw) << 2);

    const uint32_t* gA = Af + (size_t)(brow + srow)*512 + sh*8;
    const uint32_t* gB = Bf + (size_t)(bcol + srow)*512 + sh*8;

#define FSTAGE(s, B) do { \
        int o = (s) << 4; \
        cpa16(sb + 4*((B) + st0),        gA + o); cpa16(sb + 4*((B) + st1),        gA + o + 4); \
        cpa16(sb + 4*((B) + 2048 + st0), gB + o); cpa16(sb + 4*((B) + 2048 + st1), gB + o + 4); \
        CP_COMMIT; } while(0)

    float acc[4][4][4];
#pragma unroll
    for (int mt = 0; mt < 4; mt++)
#pragma unroll
        for (int nt = 0; nt < 4; nt++)
#pragma unroll
            for (int j = 0; j < 4; j++) acc[mt][nt][j] = 0.f;

    FSTAGE(0, 0);

    for (int it = 0; it < 32; it++){
        const int B = (it & 1) << 12;
        CP_WAIT0;
        __syncthreads();
        if (it < 31) FSTAGE(it + 1, ((it + 1) & 1) << 12);

        uint32_t bv[4][4];
#pragma unroll
        for (int nt = 0; nt < 4; nt++){
            int rB = wx*32 + nt*8 + (lane & 7);
            ldsm4(bv[nt], sb + 4*(B + 2048 + swo(rB, lane >> 3)));
        }
#pragma unroll
        for (int kc = 0; kc < 2; kc++){
#pragma unroll
            for (int mt = 0; mt < 4; mt++){
                uint32_t av[4];
                int rA = wy*64 + mt*16 + (lane & 15);
                ldsm4(av, sb + 4*(B + swo(rA, 2*kc + (lane >> 4))));
#pragma unroll
                for (int nt = 0; nt < 4; nt++)
                    mmah(acc[mt][nt], av[0],av[1],av[2],av[3], bv[nt][2*kc], bv[nt][2*kc+1]);
            }
        }
    }
#undef FSTAGE

#pragma unroll
    for (int mt = 0; mt < 4; mt++)
#pragma unroll
        for (int nt = 0; nt < 4; nt++){
            int row = brow + wy*64 + mt*16 + (lane >> 2);
            int col = bcol + wx*32 + nt*8 + ((lane & 3) << 1);
            float b0 = bias[col], b1 = bias[col+1];
            float v0 = acc[mt][nt][0] + b0, v1 = acc[mt][nt][1] + b1;
            float v2 = acc[mt][nt][2] + b0, v3 = acc[mt][nt][3] + b1;
            if (of){
                *(float2*)(of + (size_t)row*DM + col)     = make_float2(v0, v1);
                *(float2*)(of + (size_t)(row+8)*DM + col) = make_float2(v2, v3);
            } else {
                oh[(size_t)row*512 + (col>>1)]     = packf16(v0, v1);
                oh[(size_t)(row+8)*512 + (col>>1)] = packf16(v2, v3);
            }
        }
}

// merged Q/K/V projection: z=0 Q (bf3), z=1 K (bf3), z=2 V (f16)
__global__ __launch_bounds__(256, 2) void proj_qkv(
    const float* __restrict__ bq, const float* __restrict__ bk,
    const float* __restrict__ bv)
{
    __shared__ uint32_t S[16384];
    const int z = blockIdx.z;
    if (z == 2){
        proj_f16_body(g_xf, g_wtf, bv, g_Vf, nullptr, S);
    } else {
        proj_bf3_body(g_xh + (size_t)z*MR*512, g_xl + (size_t)z*MR*512,
                      g_wth + (size_t)z*DM*512, g_wtl + (size_t)z*DM*512,
                      z ? bk : bq, z ? g_Kf : g_Qf, S);
    }
}

// output projection (f32 out)
__global__ __launch_bounds__(256, 2) void proj_out(const float* __restrict__ bo,
                                                   float* __restrict__ out)
{
    __shared__ uint32_t S[8192];
    proj_f16_body(g_Aof, g_wtf + (size_t)DM*512, bo, nullptr, out, S);
}

// ---------------------------------------------------------------------------
// colstats: per-key-column max/sumexp over all queries. fp16 single-pass QK.
// cr carries an extra x256 to keep E in fp16 normal range.
// ---------------------------------------------------------------------------
__global__ __launch_bounds__(256, 2) void colstats(float* __restrict__ cm,
                                                   float* __restrict__ cr)
{
    __shared__ uint32_t S[8192];
    const int tid = threadIdx.x, lane = tid & 31, w = tid >> 5;
    const int bh = blockIdx.x, kt0 = blockIdx.y << 7;
    const int b = bh >> 4, h = bh & 15;
    const uint32_t sb = smem_u32(S);

    uint2 kb[2][4];
#pragma unroll
    for (int nt2 = 0; nt2 < 2; nt2++)
#pragma unroll
        for (int kc = 0; kc < 4; kc++){
            int key = kt0 + w*16 + nt2*8 + (lane >> 2);
            size_t o = (size_t)(b*SSQ + key)*512 + h*32 + kc*8 + (lane & 3);
            kb[nt2][kc] = make_uint2(g_Kf[o], g_Kf[o+4]);
        }

    const int srow = tid >> 1, sh = tid & 1;
    const int sw = (srow >> 1) & 3;
    const int st0 = (srow << 4) + (((2*sh)   ^ sw) << 2);
    const int st1 = (srow << 4) + (((2*sh+1) ^ sw) << 2);

#define QSTAGE(qt, B) do { \
        _Pragma("unroll") \
        for (int dblk = 0; dblk < 2; dblk++){ \
            const uint32_t* src = g_Qf \
                + (size_t)(b*SSQ + (qt)*128 + srow)*512 + h*32 + dblk*16 + sh*8; \
            int base = (B) + dblk*2048; \
            cpa16(sb + 4*(base + st0), src); \
            cpa16(sb + 4*(base + st1), src + 4); \
        } \
        CP_COMMIT; } while(0)

    float mst[4] = {-1e30f, -1e30f, -1e30f, -1e30f};
    float zst[4] = {0.f, 0.f, 0.f, 0.f};

    QSTAGE(0, 0);

    for (int qt = 0; qt < 16; qt++){
        const int B = (qt & 1) << 12;
        CP_WAIT0;
        __syncthreads();
        if (qt < 15) QSTAGE(qt + 1, ((qt + 1) & 1) << 12);

        float acc[8][2][4];
#pragma unroll
        for (int mt = 0; mt < 8; mt++)
#pragma unroll
            for (int nt2 = 0; nt2 < 2; nt2++)
#pragma unroll
                for (int j = 0; j < 4; j++) acc[mt][nt2][j] = 0.f;

#pragma unroll
        for (int mt = 0; mt < 8; mt++)
#pragma unroll
            for (int kcd = 0; kcd < 4; kcd++){
                int dblk = kcd >> 1, kc = kcd & 1;
                uint32_t qf[4];
                int rA = mt*16 + (lane & 15);
                int cA = 2*kc + (lane >> 4);
                ldsm4(qf, sb + 4*(B + dblk*2048 + swo(rA, cA)));
#pragma unroll
                for (int nt2 = 0; nt2 < 2; nt2++)
                    mmah(acc[mt][nt2], qf[0],qf[1],qf[2],qf[3], kb[nt2][kcd].x, kb[nt2][kcd].y);
            }

#pragma unroll
        for (int nt2 = 0; nt2 < 2; nt2++)
#pragma unroll
            for (int hh = 0; hh < 2; hh++){
                int si = nt2*2 + hh;
                float tmax = -1e30f;
#pragma unroll
                for (int mt = 0; mt < 8; mt++)
                    tmax = fmaxf(tmax, fmaxf(acc[mt][nt2][hh], acc[mt][nt2][hh+2]));
                tmax = fmaxf(tmax, __shfl_xor_sync(0xffffffffu, tmax, 4));
                tmax = fmaxf(tmax, __shfl_xor_sync(0xffffffffu, tmax, 8));
                tmax = fmaxf(tmax, __shfl_xor_sync(0xffffffffu, tmax, 16));
                float mn = fmaxf(mst[si], tmax);
                float ts = 0.f;
#pragma unroll
                for (int mt = 0; mt < 8; mt++)
                    ts += __expf(acc[mt][nt2][hh] - mn) + __expf(acc[mt][nt2][hh+2] - mn);
                ts += __shfl_xor_sync(0xffffffffu, ts, 4);
                ts += __shfl_xor_sync(0xffffffffu, ts, 8);
                ts += __shfl_xor_sync(0xffffffffu, ts, 16);
                zst[si] = zst[si] * __expf(mst[si] - mn) + ts;
                mst[si] = mn;
            }
    }
#undef QSTAGE

    if (lane < 4){
#pragma unroll
        for (int nt2 = 0; nt2 < 2; nt2++)
#pragma unroll
            for (int hh = 0; hh < 2; hh++){
                int col = kt0 + w*16 + nt2*8 + lane*2 + hh;
                cm[(size_t)bh*SSQ + col] = mst[nt2*2 + hh];
                cr[(size_t)bh*SSQ + col] = 32.0f / zst[nt2*2 + hh];
            }
    }
}

// ---------------------------------------------------------------------------
// attn: QK^T (fp16 1-pass) + exp-scale + E@V (fp16 1-pass). Q resident.
// smem u32: Qf@0 (4096); buf b @4096+b*4240: Kf 2056 | Vf 2056 | stats 128
// ---------------------------------------------------------------------------
#define AT_U32   (4096 + 2*4240)
#define AT_BYTES (AT_U32*4)

__global__ __launch_bounds__(256, 2) void attn(const float* __restrict__ cm,
                                               const float* __restrict__ cr)
{
    extern __shared__ uint32_t su[];
    const uint32_t sb = smem_u32(su);
    const int tid = threadIdx.x, lane = tid & 31, w = tid >> 5;
    const int g = lane >> 2, t = lane & 3;
    const int bh = blockIdx.x, qt0 = blockIdx.y << 7;
    const int b = bh >> 4, h = bh & 15;

    // stage Q resident (fp16 single)
    {
        const int srow = tid >> 1, sh = tid & 1;
        const int sw = (srow >> 1) & 3;
        const int st0 = (srow << 4) + (((2*sh)   ^ sw) << 2);
        const int st1 = (srow << 4) + (((2*sh+1) ^ sw) << 2);
#pragma unroll
        for (int dblk = 0; dblk < 2; dblk++){
            const uint32_t* src = g_Qf
                + (size_t)(b*SSQ + qt0 + srow)*512 + h*32 + dblk*16 + sh*8;
            su[dblk*2048 + st0] = src[0]; su[dblk*2048 + st0 + 1] = src[1];
            su[dblk*2048 + st0 + 2] = src[2]; su[dblk*2048 + st0 + 3] = src[3];
            su[dblk*2048 + st1] = src[4]; su[dblk*2048 + st1 + 1] = src[5];
            su[dblk*2048 + st1 + 2] = src[6]; su[dblk*2048 + st1 + 3] = src[7];
        }
    }

    const int krow = tid >> 2, kdb = (tid >> 1) & 1, khh = tid & 1;
    const int ksw = (krow >> 1) & 3;
    const int kst0 = (krow << 4) + (((2*khh)   ^ ksw) << 2);
    const int kst1 = (krow << 4) + (((2*khh+1) ^ ksw) << 2);

#define KSTAGE(kt, buf) do { \
        size_t go = (size_t)(b*SSQ + (kt)*64 + krow)*512 + h*32 + kdb*16 + khh*8; \
        int kb0 = 4096 + (buf)*4240 + kdb*1028; \
        cpa16(sb + 4*(kb0 + kst0), g_Kf + go); \
        cpa16(sb + 4*(kb0 + kst1), g_Kf + go + 4); \
        cpa16(sb + 4*(kb0 + 2056 + kst0), g_Vf + go); \
        cpa16(sb + 4*(kb0 + 2056 + kst1), g_Vf + go + 4); \
        if (tid < 16) \
            cpa16(sb + 4*(4096 + (buf)*4240 + 4112 + tid*4), cm + (size_t)bh*SSQ + (kt)*64 + tid*4); \
        else if (tid < 32) \
            cpa16(sb + 4*(4096 + (buf)*4240 + 4176 + (tid-16)*4), cr + (size_t)bh*SSQ + (kt)*64 + (tid-16)*4); \
        CP_COMMIT; } while(0)

    float accO[8][4];
#pragma unroll
    for (int nt = 0; nt < 8; nt++)
#pragma unroll
        for (int j = 0; j < 4; j++) accO[nt][j] = 0.f;

    KSTAGE(0, 0);

    for (int kt = 0; kt < 32; kt++){
        const int buf = kt & 1;
        CP_WAIT0;
        __syncthreads();
        if (kt < 31) KSTAGE(kt + 1, buf ^ 1);

        const int Kb = 4096 + buf*4240;
        const int Vb = Kb + 2056;
        const float* mS = (const float*)(su + Kb + 4112);
        const float* rS = (const float*)(su + Kb + 4176);

        float accs[8][4];
#pragma unroll
        for (int nt = 0; nt < 8; nt++)
#pragma unroll
            for (int j = 0; j < 4; j++) accs[nt][j] = 0.f;

#pragma unroll
        for (int kcd = 0; kcd < 4; kcd++){
            int dblk = kcd >> 1, kc = kcd & 1;
            uint32_t qf[4];
            ldsm4(qf, sb + 4*(dblk*2048 + swo(w*16 + (lane & 15), 2*kc + (lane >> 4))));
            int rK = lane & 7;
            int cK = 2*kc + ((lane >> 3) & 1);
            int ntSel = lane >> 4;
#pragma unroll
            for (int ntp = 0; ntp < 4; ntp++){
                int ntX = 2*ntp + ntSel;
                uint32_t kf[4];
                ldsm4(kf, sb + 4*(Kb + dblk*1028 + swo(ntX*8 + rK, cK)));
                mmah(accs[2*ntp],   qf[0],qf[1],qf[2],qf[3], kf[0], kf[1]);
                mmah(accs[2*ntp+1], qf[0],qf[1],qf[2],qf[3], kf[2], kf[3]);
            }
        }

#pragma unroll
        for (int kp = 0; kp < 2; kp++){
            uint32_t EF[2][4];
#pragma unroll
            for (int ntl = 0; ntl < 4; ntl++){
                int nt = 4*kp + ntl;
                int kcl = ntl >> 1, rb = (ntl & 1) << 1;
                int c0 = nt*8 + t*2, c1 = c0 + 1;
                float m0 = mS[c0], m1 = mS[c1], r0 = rS[c0], r1 = rS[c1];
                float e00 = __expf(accs[nt][0] - m0) * r0;
                float e01 = __expf(accs[nt][1] - m1) * r1;
                float e10 = __expf(accs[nt][2] - m0) * r0;
                float e11 = __expf(accs[nt][3] - m1) * r1;
                EF[kcl][rb]   = packf16(e00, e01);
                EF[kcl][rb+1] = packf16(e10, e11);
            }
#pragma unroll
            for (int ntd = 0; ntd < 8; ntd++){
                int dbd = ntd >> 2, ch = ntd & 3;
                uint32_t vf[4];
                ldsm4t(vf, sb + 4*(Vb + dbd*1028 + swo(kp*32 + lane, ch)));
                mmah(accO[ntd], EF[0][0],EF[0][1],EF[0][2],EF[0][3], vf[0], vf[1]);
                mmah(accO[ntd], EF[1][0],EF[1][1],EF[1][2],EF[1][3], vf[2], vf[3]);
            }
        }
    }
#undef KSTAGE

    const float sc = 1.0f/256.0f;
    const int row = qt0 + w*16 + g;
#pragma unroll
    for (int nt = 0; nt < 8; nt++){
        int col = nt*8 + t*2;
        g_Aof[(size_t)(b*SSQ + row)*512 + h*32 + (col>>1)] =
            packf16(accO[nt][0]*sc, accO[nt][1]*sc);
        g_Aof[(size_t)(b*SSQ + row + 8)*512 + h*32 + (col>>1)] =
            packf16(accO[nt][2]*sc, accO[nt][3]*sc);
    }
}

// ---------------------------------------------------------------------------
// Launch
// ---------------------------------------------------------------------------
extern "C" void kernel_launch(void* const* d_in, const int* in_sizes, int n_in,
                              void* d_out, int out_size)
{
    const float* qin = (const float*)d_in[0];
    const float* kin = (const float*)d_in[1];
    const float* vin = (const float*)d_in[2];
    const float* Wq  = (const float*)d_in[3];
    const float* bq  = (const float*)d_in[4];
    const float* Wk  = (const float*)d_in[5];
    const float* bk  = (const float*)d_in[6];
    const float* Wv  = (const float*)d_in[7];
    const float* bv  = (const float*)d_in[8];
    const float* Wo  = (const float*)d_in[9];
    const float* bo  = (const float*)d_in[10];

    float *cm, *cr;
    cudaGetSymbolAddress((void**)&cm, g_cm);
    cudaGetSymbolAddress((void**)&cr, g_cr);

    cudaFuncSetAttribute(attn, cudaFuncAttributeMaxDynamicSharedMemorySize, AT_BYTES);

    inprep3<<<dim3(MR*512/256, 3), 256>>>(qin, kin, vin);
    wprep_all<<<dim3(16, 32, 4), 256>>>(Wq, Wk, Wv, Wo);

    proj_qkv<<<dim3(DM/128, MR/128, 3), 256>>>(bq, bk, bv);

    colstats<<<dim3(BB*NH, SSQ/128), 256>>>(cm, cr);

    attn<<<dim3(BB*NH, SSQ/128), 256, AT_BYTES>>>(cm, cr);

    proj_out<<<dim3(DM/128, MR/128), 256>>>(bo, (float*)d_out);
}

// round 17
// speedup vs baseline: 1.0205x; 1.0205x over previous
#include <cuda_runtime.h>
#include <cuda_bf16.h>
#include <cuda_fp16.h>
#include <stdint.h>

#define BB 4
#define SSQ 2048
#define DM 1024
#define NH 16
#define MR (BB*SSQ)
#define LOG2E 1.4426950408889634f

// ---------------------------------------------------------------------------
// Scratch
// ---------------------------------------------------------------------------
__device__ uint32_t g_wth[2*DM*512], g_wtl[2*DM*512];   // Wq,Wk transposed, bf16 split
__device__ uint32_t g_wtf[2*DM*512];                    // Wv,Wo transposed, fp16
__device__ uint32_t g_xh[2u*MR*512], g_xl[2u*MR*512];   // q,k inputs bf16 split
__device__ uint32_t g_xf[MR*512];                       // v input fp16
__device__ uint32_t g_Qf[MR*512], g_Kf[MR*512], g_Vf[MR*512], g_Aof[MR*512];
__device__ float g_cm[BB*NH*SSQ], g_cr[BB*NH*SSQ];

// ---------------------------------------------------------------------------
// helpers
// ---------------------------------------------------------------------------
__device__ __forceinline__ void split2(float x, float y, uint32_t& hi, uint32_t& lo){
    __nv_bfloat16 hx = __float2bfloat16(x);
    __nv_bfloat16 hy = __float2bfloat16(y);
    float rx = x - __bfloat162float(hx);
    float ry = y - __bfloat162float(hy);
    __nv_bfloat162 h2 = __halves2bfloat162(hx, hy);
    __nv_bfloat162 l2 = __halves2bfloat162(__float2bfloat16(rx), __float2bfloat16(ry));
    hi = *reinterpret_cast<uint32_t*>(&h2);
    lo = *reinterpret_cast<uint32_t*>(&l2);
}
__device__ __forceinline__ uint32_t packf16(float x, float y){
    __half2 h = __floats2half2_rn(x, y);
    return *reinterpret_cast<uint32_t*>(&h);
}
__device__ __forceinline__ float ex2f(float x){
    float r;
    asm("ex2.approx.f32 %0, %1;" : "=f"(r) : "f"(x));
    return r;
}

__device__ __forceinline__ void mma16(float* d,
    uint32_t a0, uint32_t a1, uint32_t a2, uint32_t a3, uint32_t b0, uint32_t b1)
{
    asm volatile(
        "mma.sync.aligned.m16n8k16.row.col.f32.bf16.bf16.f32 "
        "{%0,%1,%2,%3}, {%4,%5,%6,%7}, {%8,%9}, {%0,%1,%2,%3};\n"
        : "+f"(d[0]), "+f"(d[1]), "+f"(d[2]), "+f"(d[3])
        : "r"(a0), "r"(a1), "r"(a2), "r"(a3), "r"(b0), "r"(b1));
}
__device__ __forceinline__ void mmah(float* d,
    uint32_t a0, uint32_t a1, uint32_t a2, uint32_t a3, uint32_t b0, uint32_t b1)
{
    asm volatile(
        "mma.sync.aligned.m16n8k16.row.col.f32.f16.f16.f32 "
        "{%0,%1,%2,%3}, {%4,%5,%6,%7}, {%8,%9}, {%0,%1,%2,%3};\n"
        : "+f"(d[0]), "+f"(d[1]), "+f"(d[2]), "+f"(d[3])
        : "r"(a0), "r"(a1), "r"(a2), "r"(a3), "r"(b0), "r"(b1));
}

__device__ __forceinline__ uint32_t smem_u32(const void* p){
    uint32_t a;
    asm("{ .reg .u64 t; cvta.to.shared.u64 t, %1; cvt.u32.u64 %0, t; }" : "=r"(a) : "l"(p));
    return a;
}
__device__ __forceinline__ void ldsm4(uint32_t* r, uint32_t addr){
    asm volatile("ldmatrix.sync.aligned.m8n8.x4.shared.b16 {%0,%1,%2,%3}, [%4];"
        : "=r"(r[0]), "=r"(r[1]), "=r"(r[2]), "=r"(r[3]) : "r"(addr));
}
__device__ __forceinline__ void ldsm4t(uint32_t* r, uint32_t addr){
    asm volatile("ldmatrix.sync.aligned.m8n8.x4.trans.shared.b16 {%0,%1,%2,%3}, [%4];"
        : "=r"(r[0]), "=r"(r[1]), "=r"(r[2]), "=r"(r[3]) : "r"(addr));
}
__device__ __forceinline__ void cpa16(uint32_t dst, const void* src){
    asm volatile("cp.async.cg.shared.global [%0], [%1], 16;\n" :: "r"(dst), "l"(src));
}
#define CP_COMMIT asm volatile("cp.async.commit_group;\n" ::: "memory")
#define CP_WAIT0  asm volatile("cp.async.wait_group 0;\n" ::: "memory")

__device__ __forceinline__ int swo(int r, int c){
    return (r << 4) + (((c ^ ((r >> 1) & 3))) << 2);
}

// ---------------------------------------------------------------------------
// prepass
// ---------------------------------------------------------------------------
__global__ __launch_bounds__(256) void inprep3(const float* __restrict__ q,
    const float* __restrict__ k, const float* __restrict__ v)
{
    const int y = blockIdx.y;
    size_t i = (size_t)blockIdx.x*256 + threadIdx.x;
    if (y < 2){
        const float* in = y ? k : q;
        float2 vv = *(const float2*)(in + 2*i);
        uint32_t hh, ll; split2(vv.x, vv.y, hh, ll);
        g_xh[(size_t)y*MR*512 + i] = hh;
        g_xl[(size_t)y*MR*512 + i] = ll;
    } else {
        float2 vv = *(const float2*)(v + 2*i);
        g_xf[i] = packf16(vv.x, vv.y);
    }
}

// merged W prep: z=0,1 -> bf16 split (Wq,Wk); z=2,3 -> fp16 (Wv,Wo)
__global__ __launch_bounds__(256) void wprep_all(const float* __restrict__ Wq,
    const float* __restrict__ Wk, const float* __restrict__ Wv,
    const float* __restrict__ Wo)
{
    __shared__ float t[64][33];
    const int z = blockIdx.z;
    const float* W = (z == 0) ? Wq : (z == 1) ? Wk : (z == 2) ? Wv : Wo;
    const int k0 = blockIdx.x << 6, n0 = blockIdx.y << 5;
    const int tid = threadIdx.x;
#pragma unroll
    for (int i = 0; i < 8; i++){
        int v = i*256 + tid;
        t[v >> 5][v & 31] = W[(size_t)(k0 + (v >> 5))*DM + n0 + (v & 31)];
    }
    __syncthreads();
    const int n = tid >> 3, pi = (tid & 7) << 2;
    if (z < 2){
        uint4 H, L; uint32_t h, l;
        split2(t[2*pi][n],   t[2*pi+1][n], h, l); H.x = h; L.x = l;
        split2(t[2*pi+2][n], t[2*pi+3][n], h, l); H.y = h; L.y = l;
        split2(t[2*pi+4][n], t[2*pi+5][n], h, l); H.z = h; L.z = l;
        split2(t[2*pi+6][n], t[2*pi+7][n], h, l); H.w = h; L.w = l;
        size_t o = (size_t)z*DM*512 + (size_t)(n0 + n)*512 + (k0 >> 1) + pi;
        *(uint4*)(g_wth + o) = H;
        *(uint4*)(g_wtl + o) = L;
    } else {
        uint4 H;
        H.x = packf16(t[2*pi][n],   t[2*pi+1][n]);
        H.y = packf16(t[2*pi+2][n], t[2*pi+3][n]);
        H.z = packf16(t[2*pi+4][n], t[2*pi+5][n]);
        H.w = packf16(t[2*pi+6][n], t[2*pi+7][n]);
        *(uint4*)(g_wtf + (size_t)(z-2)*DM*512 + (size_t)(n0 + n)*512 + (k0 >> 1) + pi) = H;
    }
}

// ---------------------------------------------------------------------------
// proj_bf3_body: exact 3-pass split-bf16 GEMM, fp16 out (scaled by oscale).
// 2-stage cp.async, pass-major mma ordering. 256 thr, 8 warps 2x4, warp 64x32.
// ---------------------------------------------------------------------------
__device__ __forceinline__ void proj_bf3_body(
    const uint32_t* __restrict__ Ah, const uint32_t* __restrict__ Al,
    const uint32_t* __restrict__ Bh, const uint32_t* __restrict__ Bl,
    const float* __restrict__ bias, uint32_t* __restrict__ oh,
    float oscale, uint32_t* S)
{
    const int tid = threadIdx.x, lane = tid & 31, w = tid >> 5;
    const int wy = w >> 2, wx = w & 3;
    const int brow = blockIdx.y << 7, bcol = blockIdx.x << 7;
    const uint32_t sb = smem_u32(S);

    const int srow = tid >> 1, sh = tid & 1;
    const int sw = (srow >> 1) & 3;
    const int st0 = (srow << 4) + (((2*sh)   ^ sw) << 2);
    const int st1 = (srow << 4) + (((2*sh+1) ^ sw) << 2);

    const uint32_t* gA0 = Ah + (size_t)(brow + srow)*512 + sh*8;
    const uint32_t* gA1 = Al + (size_t)(brow + srow)*512 + sh*8;
    const uint32_t* gB0 = Bh + (size_t)(bcol + srow)*512 + sh*8;
    const uint32_t* gB1 = Bl + (size_t)(bcol + srow)*512 + sh*8;

#define PSTAGE(s, B) do { \
        int o = (s) << 4; \
        cpa16(sb + 4*((B) + st0),        gA0 + o); cpa16(sb + 4*((B) + st1),        gA0 + o + 4); \
        cpa16(sb + 4*((B) + 2048 + st0), gA1 + o); cpa16(sb + 4*((B) + 2048 + st1), gA1 + o + 4); \
        cpa16(sb + 4*((B) + 4096 + st0), gB0 + o); cpa16(sb + 4*((B) + 4096 + st1), gB0 + o + 4); \
        cpa16(sb + 4*((B) + 6144 + st0), gB1 + o); cpa16(sb + 4*((B) + 6144 + st1), gB1 + o + 4); \
        CP_COMMIT; } while(0)

    float acc[4][4][4];
#pragma unroll
    for (int mt = 0; mt < 4; mt++)
#pragma unroll
        for (int nt = 0; nt < 4; nt++)
#pragma unroll
            for (int j = 0; j < 4; j++) acc[mt][nt][j] = 0.f;

    PSTAGE(0, 0);

    for (int it = 0; it < 32; it++){
        const int B = (it & 1) << 13;
        CP_WAIT0;
        __syncthreads();
        if (it < 31) PSTAGE(it + 1, ((it + 1) & 1) << 13);

        uint32_t bhv[4][4], blv[4][4];
#pragma unroll
        for (int nt = 0; nt < 4; nt++){
            int rB = wx*32 + nt*8 + (lane & 7);
            int cB = lane >> 3;
            uint32_t ad = sb + 4*(B + 4096 + swo(rB, cB));
            ldsm4(bhv[nt], ad);
            ldsm4(blv[nt], ad + 2048*4);
        }
#pragma unroll
        for (int kc = 0; kc < 2; kc++){
#pragma unroll
            for (int mt = 0; mt < 4; mt++){
                uint32_t ahv[4], alv[4];
                int rA = wy*64 + mt*16 + (lane & 15);
                int cA = 2*kc + (lane >> 4);
                uint32_t ad = sb + 4*(B + swo(rA, cA));
                ldsm4(ahv, ad);
                ldsm4(alv, ad + 2048*4);
#pragma unroll
                for (int nt = 0; nt < 4; nt++)
                    mma16(acc[mt][nt], ahv[0],ahv[1],ahv[2],ahv[3], bhv[nt][2*kc], bhv[nt][2*kc+1]);
#pragma unroll
                for (int nt = 0; nt < 4; nt++)
                    mma16(acc[mt][nt], alv[0],alv[1],alv[2],alv[3], bhv[nt][2*kc], bhv[nt][2*kc+1]);
#pragma unroll
                for (int nt = 0; nt < 4; nt++)
                    mma16(acc[mt][nt], ahv[0],ahv[1],ahv[2],ahv[3], blv[nt][2*kc], blv[nt][2*kc+1]);
            }
        }
    }
#undef PSTAGE

#pragma unroll
    for (int mt = 0; mt < 4; mt++)
#pragma unroll
        for (int nt = 0; nt < 4; nt++){
            int row = brow + wy*64 + mt*16 + (lane >> 2);
            int col = bcol + wx*32 + nt*8 + ((lane & 3) << 1);
            float b0 = bias[col], b1 = bias[col+1];
            oh[(size_t)row*512 + (col>>1)] =
                packf16((acc[mt][nt][0] + b0)*oscale, (acc[mt][nt][1] + b1)*oscale);
            oh[(size_t)(row+8)*512 + (col>>1)] =
                packf16((acc[mt][nt][2] + b0)*oscale, (acc[mt][nt][3] + b1)*oscale);
        }
}

// ---------------------------------------------------------------------------
// proj_f16_body: single-pass fp16 GEMM, 2-stage cp.async.
// ---------------------------------------------------------------------------
__device__ __forceinline__ void proj_f16_body(
    const uint32_t* __restrict__ Af, const uint32_t* __restrict__ Bf,
    const float* __restrict__ bias, uint32_t* __restrict__ oh,
    float* __restrict__ of, uint32_t* S)
{
    const int tid = threadIdx.x, lane = tid & 31, w = tid >> 5;
    const int wy = w >> 2, wx = w & 3;
    const int brow = blockIdx.y << 7, bcol = blockIdx.x << 7;
    const uint32_t sb = smem_u32(S);

    const int srow = tid >> 1, sh = tid & 1;
    const int sw = (srow >> 1) & 3;
    const int st0 = (srow << 4) + (((2*sh)   ^ sw) << 2);
    const int st1 = (srow << 4) + (((2*sh+1) ^ sw) << 2);

    const uint32_t* gA = Af + (size_t)(brow + srow)*512 + sh*8;
    const uint32_t* gB = Bf + (size_t)(bcol + srow)*512 + sh*8;

#define FSTAGE(s, B) do { \
        int o = (s) << 4; \
        cpa16(sb + 4*((B) + st0),        gA + o); cpa16(sb + 4*((B) + st1),        gA + o + 4); \
        cpa16(sb + 4*((B) + 2048 + st0), gB + o); cpa16(sb + 4*((B) + 2048 + st1), gB + o + 4); \
        CP_COMMIT; } while(0)

    float acc[4][4][4];
#pragma unroll
    for (int mt = 0; mt < 4; mt++)
#pragma unroll
        for (int nt = 0; nt < 4; nt++)
#pragma unroll
            for (int j = 0; j < 4; j++) acc[mt][nt][j] = 0.f;

    FSTAGE(0, 0);

    for (int it = 0; it < 32; it++){
        const int B = (it & 1) << 12;
        CP_WAIT0;
        __syncthreads();
        if (it < 31) FSTAGE(it + 1, ((it + 1) & 1) << 12);

        uint32_t bv[4][4];
#pragma unroll
        for (int nt = 0; nt < 4; nt++){
            int rB = wx*32 + nt*8 + (lane & 7);
            ldsm4(bv[nt], sb + 4*(B + 2048 + swo(rB, lane >> 3)));
        }
#pragma unroll
        for (int kc = 0; kc < 2; kc++){
#pragma unroll
            for (int mt = 0; mt < 4; mt++){
                uint32_t av[4];
                int rA = wy*64 + mt*16 + (lane & 15);
                ldsm4(av, sb + 4*(B + swo(rA, 2*kc + (lane >> 4))));
#pragma unroll
                for (int nt = 0; nt < 4; nt++)
                    mmah(acc[mt][nt], av[0],av[1],av[2],av[3], bv[nt][2*kc], bv[nt][2*kc+1]);
            }
        }
    }
#undef FSTAGE

#pragma unroll
    for (int mt = 0; mt < 4; mt++)
#pragma unroll
        for (int nt = 0; nt < 4; nt++){
            int row = brow + wy*64 + mt*16 + (lane >> 2);
            int col = bcol + wx*32 + nt*8 + ((lane & 3) << 1);
            float b0 = bias[col], b1 = bias[col+1];
            float v0 = acc[mt][nt][0] + b0, v1 = acc[mt][nt][1] + b1;
            float v2 = acc[mt][nt][2] + b0, v3 = acc[mt][nt][3] + b1;
            if (of){
                *(float2*)(of + (size_t)row*DM + col)     = make_float2(v0, v1);
                *(float2*)(of + (size_t)(row+8)*DM + col) = make_float2(v2, v3);
            } else {
                oh[(size_t)row*512 + (col>>1)]     = packf16(v0, v1);
                oh[(size_t)(row+8)*512 + (col>>1)] = packf16(v2, v3);
            }
        }
}

// merged Q/K/V projection: z=0 Q (bf3, x log2e), z=1 K (bf3), z=2 V (f16)
__global__ __launch_bounds__(256, 2) void proj_qkv(
    const float* __restrict__ bq, const float* __restrict__ bk,
    const float* __restrict__ bv)
{
    __shared__ uint32_t S[16384];
    const int z = blockIdx.z;
    if (z == 2){
        proj_f16_body(g_xf, g_wtf, bv, g_Vf, nullptr, S);
    } else {
        proj_bf3_body(g_xh + (size_t)z*MR*512, g_xl + (size_t)z*MR*512,
                      g_wth + (size_t)z*DM*512, g_wtl + (size_t)z*DM*512,
                      z ? bk : bq, z ? g_Kf : g_Qf,
                      z ? 1.0f : LOG2E, S);
    }
}

// output projection (f32 out)
__global__ __launch_bounds__(256, 2) void proj_out(const float* __restrict__ bo,
                                                   float* __restrict__ out)
{
    __shared__ uint32_t S[8192];
    proj_f16_body(g_Aof, g_wtf + (size_t)DM*512, bo, nullptr, out, S);
}

// ---------------------------------------------------------------------------
// colstats: per-key-column max/sumexp over all queries. Scores arrive
// pre-scaled by log2e -> raw ex2. Per-thread deferred online stats; one
// cross-lane merge at the end. cr carries extra x256 for fp16-E range.
// ---------------------------------------------------------------------------
__global__ __launch_bounds__(256, 2) void colstats(float* __restrict__ cm,
                                                   float* __restrict__ cr)
{
    __shared__ uint32_t S[8192];
    const int tid = threadIdx.x, lane = tid & 31, w = tid >> 5;
    const int bh = blockIdx.x, kt0 = blockIdx.y << 7;
    const int b = bh >> 4, h = bh & 15;
    const uint32_t sb = smem_u32(S);

    uint2 kb[2][4];
#pragma unroll
    for (int nt2 = 0; nt2 < 2; nt2++)
#pragma unroll
        for (int kc = 0; kc < 4; kc++){
            int key = kt0 + w*16 + nt2*8 + (lane >> 2);
            size_t o = (size_t)(b*SSQ + key)*512 + h*32 + kc*8 + (lane & 3);
            kb[nt2][kc] = make_uint2(g_Kf[o], g_Kf[o+4]);
        }

    const int srow = tid >> 1, sh = tid & 1;
    const int sw = (srow >> 1) & 3;
    const int st0 = (srow << 4) + (((2*sh)   ^ sw) << 2);
    const int st1 = (srow << 4) + (((2*sh+1) ^ sw) << 2);

#define QSTAGE(qt, B) do { \
        _Pragma("unroll") \
        for (int dblk = 0; dblk < 2; dblk++){ \
            const uint32_t* src = g_Qf \
                + (size_t)(b*SSQ + (qt)*128 + srow)*512 + h*32 + dblk*16 + sh*8; \
            int base = (B) + dblk*2048; \
            cpa16(sb + 4*(base + st0), src); \
            cpa16(sb + 4*(base + st1), src + 4); \
        } \
        CP_COMMIT; } while(0)

    float mst[4] = {-1e30f, -1e30f, -1e30f, -1e30f};
    float zst[4] = {0.f, 0.f, 0.f, 0.f};

    QSTAGE(0, 0);

    for (int qt = 0; qt < 16; qt++){
        const int B = (qt & 1) << 12;
        CP_WAIT0;
        __syncthreads();
        if (qt < 15) QSTAGE(qt + 1, ((qt + 1) & 1) << 12);

        float acc[8][2][4];
#pragma unroll
        for (int mt = 0; mt < 8; mt++)
#pragma unroll
            for (int nt2 = 0; nt2 < 2; nt2++)
#pragma unroll
                for (int j = 0; j < 4; j++) acc[mt][nt2][j] = 0.f;

#pragma unroll
        for (int mt = 0; mt < 8; mt++)
#pragma unroll
            for (int kcd = 0; kcd < 4; kcd++){
                int dblk = kcd >> 1, kc = kcd & 1;
                uint32_t qf[4];
                int rA = mt*16 + (lane & 15);
                int cA = 2*kc + (lane >> 4);
                ldsm4(qf, sb + 4*(B + dblk*2048 + swo(rA, cA)));
#pragma unroll
                for (int nt2 = 0; nt2 < 2; nt2++)
                    mmah(acc[mt][nt2], qf[0],qf[1],qf[2],qf[3], kb[nt2][kcd].x, kb[nt2][kcd].y);
            }

        // per-thread online stats (no cross-lane work inside the loop)
#pragma unroll
        for (int nt2 = 0; nt2 < 2; nt2++)
#pragma unroll
            for (int hh = 0; hh < 2; hh++){
                int si = nt2*2 + hh;
                float tmax = -1e30f;
#pragma unroll
                for (int mt = 0; mt < 8; mt++)
                    tmax = fmaxf(tmax, fmaxf(acc[mt][nt2][hh], acc[mt][nt2][hh+2]));
                float mn = fmaxf(mst[si], tmax);
                float ts = 0.f;
#pragma unroll
                for (int mt = 0; mt < 8; mt++)
                    ts += ex2f(acc[mt][nt2][hh] - mn) + ex2f(acc[mt][nt2][hh+2] - mn);
                zst[si] = zst[si] * ex2f(mst[si] - mn) + ts;
                mst[si] = mn;
            }
    }
#undef QSTAGE

    // final cross-lane merge (lanes xor 4, 8, 16 hold disjoint q-row sets)
#pragma unroll
    for (int si = 0; si < 4; si++){
        float m = mst[si], z = zst[si];
#pragma unroll
        for (int off = 4; off <= 16; off <<= 1){
            float m2 = __shfl_xor_sync(0xffffffffu, m, off);
            float z2 = __shfl_xor_sync(0xffffffffu, z, off);
            float mn = fmaxf(m, m2);
            z = z * ex2f(m - mn) + z2 * ex2f(m2 - mn);
            m = mn;
        }
        mst[si] = m; zst[si] = z;
    }

    if (lane < 4){
#pragma unroll
        for (int nt2 = 0; nt2 < 2; nt2++)
#pragma unroll
            for (int hh = 0; hh < 2; hh++){
                int col = kt0 + w*16 + nt2*8 + lane*2 + hh;
                cm[(size_t)bh*SSQ + col] = mst[nt2*2 + hh];
                cr[(size_t)bh*SSQ + col] = 32.0f / zst[nt2*2 + hh];
            }
    }
}

// ---------------------------------------------------------------------------
// attn: QK^T (fp16 1-pass, log2e-scaled scores) + ex2-scale + E@V (fp16 1-pass).
// smem u32: Qf@0 (4096); buf b @4096+b*4240: Kf 2056 | Vf 2056 | stats 128
// ---------------------------------------------------------------------------
#define AT_U32   (4096 + 2*4240)
#define AT_BYTES (AT_U32*4)

__global__ __launch_bounds__(256, 2) void attn(const float* __restrict__ cm,
                                               const float* __restrict__ cr)
{
    extern __shared__ uint32_t su[];
    const uint32_t sb = smem_u32(su);
    const int tid = threadIdx.x, lane = tid & 31, w = tid >> 5;
    const int g = lane >> 2, t = lane & 3;
    const int bh = blockIdx.x, qt0 = blockIdx.y << 7;
    const int b = bh >> 4, h = bh & 15;

    // stage Q resident (fp16 single, pre-scaled by log2e)
    {
        const int srow = tid >> 1, sh = tid & 1;
        const int sw = (srow >> 1) & 3;
        const int st0 = (srow << 4) + (((2*sh)   ^ sw) << 2);
        const int st1 = (srow << 4) + (((2*sh+1) ^ sw) << 2);
#pragma unroll
        for (int dblk = 0; dblk < 2; dblk++){
            const uint32_t* src = g_Qf
                + (size_t)(b*SSQ + qt0 + srow)*512 + h*32 + dblk*16 + sh*8;
            su[dblk*2048 + st0] = src[0]; su[dblk*2048 + st0 + 1] = src[1];
            su[dblk*2048 + st0 + 2] = src[2]; su[dblk*2048 + st0 + 3] = src[3];
            su[dblk*2048 + st1] = src[4]; su[dblk*2048 + st1 + 1] = src[5];
            su[dblk*2048 + st1 + 2] = src[6]; su[dblk*2048 + st1 + 3] = src[7];
        }
    }

    const int krow = tid >> 2, kdb = (tid >> 1) & 1, khh = tid & 1;
    const int ksw = (krow >> 1) & 3;
    const int kst0 = (krow << 4) + (((2*khh)   ^ ksw) << 2);
    const int kst1 = (krow << 4) + (((2*khh+1) ^ ksw) << 2);

#define KSTAGE(kt, buf) do { \
        size_t go = (size_t)(b*SSQ + (kt)*64 + krow)*512 + h*32 + kdb*16 + khh*8; \
        int kb0 = 4096 + (buf)*4240 + kdb*1028; \
        cpa16(sb + 4*(kb0 + kst0), g_Kf + go); \
        cpa16(sb + 4*(kb0 + kst1), g_Kf + go + 4); \
        cpa16(sb + 4*(kb0 + 2056 + kst0), g_Vf + go); \
        cpa16(sb + 4*(kb0 + 2056 + kst1), g_Vf + go + 4); \
        if (tid < 16) \
            cpa16(sb + 4*(4096 + (buf)*4240 + 4112 + tid*4), cm + (size_t)bh*SSQ + (kt)*64 + tid*4); \
        else if (tid < 32) \
            cpa16(sb + 4*(4096 + (buf)*4240 + 4176 + (tid-16)*4), cr + (size_t)bh*SSQ + (kt)*64 + (tid-16)*4); \
        CP_COMMIT; } while(0)

    float accO[8][4];
#pragma unroll
    for (int nt = 0; nt < 8; nt++)
#pragma unroll
        for (int j = 0; j < 4; j++) accO[nt][j] = 0.f;

    KSTAGE(0, 0);

    for (int kt = 0; kt < 32; kt++){
        const int buf = kt & 1;
        CP_WAIT0;
        __syncthreads();
        if (kt < 31) KSTAGE(kt + 1, buf ^ 1);

        const int Kb = 4096 + buf*4240;
        const int Vb = Kb + 2056;
        const float* mS = (const float*)(su + Kb + 4112);
        const float* rS = (const float*)(su + Kb + 4176);

        float accs[8][4];
#pragma unroll
        for (int nt = 0; nt < 8; nt++)
#pragma unroll
            for (int j = 0; j < 4; j++) accs[nt][j] = 0.f;

#pragma unroll
        for (int kcd = 0; kcd < 4; kcd++){
            int dblk = kcd >> 1, kc = kcd & 1;
            uint32_t qf[4];
            ldsm4(qf, sb + 4*(dblk*2048 + swo(w*16 + (lane & 15), 2*kc + (lane >> 4))));
            int rK = lane & 7;
            int cK = 2*kc + ((lane >> 3) & 1);
            int ntSel = lane >> 4;
#pragma unroll
            for (int ntp = 0; ntp < 4; ntp++){
                int ntX = 2*ntp + ntSel;
                uint32_t kf[4];
                ldsm4(kf, sb + 4*(Kb + dblk*1028 + swo(ntX*8 + rK, cK)));
                mmah(accs[2*ntp],   qf[0],qf[1],qf[2],qf[3], kf[0], kf[1]);
                mmah(accs[2*ntp+1], qf[0],qf[1],qf[2],qf[3], kf[2], kf[3]);
            }
        }

#pragma unroll
        for (int kp = 0; kp < 2; kp++){
            uint32_t EF[2][4];
#pragma unroll
            for (int ntl = 0; ntl < 4; ntl++){
                int nt = 4*kp + ntl;
                int kcl = ntl >> 1, rb = (ntl & 1) << 1;
                int c0 = nt*8 + t*2, c1 = c0 + 1;
                float m0 = mS[c0], m1 = mS[c1], r0 = rS[c0], r1 = rS[c1];
                float e00 = ex2f(accs[nt][0] - m0) * r0;
                float e01 = ex2f(accs[nt][1] - m1) * r1;
                float e10 = ex2f(accs[nt][2] - m0) * r0;
                float e11 = ex2f(accs[nt][3] - m1) * r1;
                EF[kcl][rb]   = packf16(e00, e01);
                EF[kcl][rb+1] = packf16(e10, e11);
            }
#pragma unroll
            for (int ntd = 0; ntd < 8; ntd++){
                int dbd = ntd >> 2, ch = ntd & 3;
                uint32_t vf[4];
                ldsm4t(vf, sb + 4*(Vb + dbd*1028 + swo(kp*32 + lane, ch)));
                mmah(accO[ntd], EF[0][0],EF[0][1],EF[0][2],EF[0][3], vf[0], vf[1]);
                mmah(accO[ntd], EF[1][0],EF[1][1],EF[1][2],EF[1][3], vf[2], vf[3]);
            }
        }
    }
#undef KSTAGE

    const float sc = 1.0f/256.0f;
    const int row = qt0 + w*16 + g;
#pragma unroll
    for (int nt = 0; nt < 8; nt++){
        int col = nt*8 + t*2;
        g_Aof[(size_t)(b*SSQ + row)*512 + h*32 + (col>>1)] =
            packf16(accO[nt][0]*sc, accO[nt][1]*sc);
        g_Aof[(size_t)(b*SSQ + row + 8)*512 + h*32 + (col>>1)] =
            packf16(accO[nt][2]*sc, accO[nt][3]*sc);
    }
}

// ---------------------------------------------------------------------------
// Launch
// ---------------------------------------------------------------------------
extern "C" void kernel_launch(void* const* d_in, const int* in_sizes, int n_in,
                              void* d_out, int out_size)
{
    const float* qin = (const float*)d_in[0];
    const float* kin = (const float*)d_in[1];
    const float* vin = (const float*)d_in[2];
    const float* Wq  = (const float*)d_in[3];
    const float* bq  = (const float*)d_in[4];
    const float* Wk  = (const float*)d_in[5];
    const float* bk  = (const float*)d_in[6];
    const float* Wv  = (const float*)d_in[7];
    const float* bv  = (const float*)d_in[8];
    const float* Wo  = (const float*)d_in[9];
    const float* bo  = (const float*)d_in[10];

    float *cm, *cr;
    cudaGetSymbolAddress((void**)&cm, g_cm);
    cudaGetSymbolAddress((void**)&cr, g_cr);

    cudaFuncSetAttribute(attn, cudaFuncAttributeMaxDynamicSharedMemorySize, AT_BYTES);

    inprep3<<<dim3(MR*512/256, 3), 256>>>(qin, kin, vin);
    wprep_all<<<dim3(16, 32, 4), 256>>>(Wq, Wk, Wv, Wo);

    proj_qkv<<<dim3(DM/128, MR/128, 3), 256>>>(bq, bk, bv);

    colstats<<<dim3(BB*NH, SSQ/128), 256>>>(cm, cr);

    attn<<<dim3(BB*NH, SSQ/128), 256, AT_BYTES>>>(cm, cr);

    proj_out<<<dim3(DM/128, MR/128), 256>>>(bo, (float*)d_out);
}